// round 1
// baseline (speedup 1.0000x reference)
#include <cuda_runtime.h>
#include <cstdint>

#define NNODES 50000
#define OUTD   128
#define HIDD   512

// ---------------- device scratch (no allocations allowed) ----------------
__device__ float4 g_S4[NNODES * (OUTD / 4)];   // 25.6 MB accumulator S[N][128]
__device__ float  g_cnt[NNODES];               // per-node edge count (as float)
__device__ float  g_WcT[OUTD * OUTD];          // (W2@W1) transposed: [k][o]
__device__ float  g_bc[OUTD];                  // W2 @ b1

// ---------------- f32x2 packed-FMA helpers ----------------
__device__ __forceinline__ unsigned long long pack2(float x, float y) {
    unsigned long long r;
    asm("mov.b64 %0, {%1, %2};" : "=l"(r) : "f"(x), "f"(y));
    return r;
}
__device__ __forceinline__ void unpack2(unsigned long long v, float& x, float& y) {
    asm("mov.b64 {%0, %1}, %2;" : "=f"(x), "=f"(y) : "l"(v));
}
__device__ __forceinline__ void ffma2(unsigned long long& d,
                                      unsigned long long a,
                                      unsigned long long b) {
    asm("fma.rn.f32x2 %0, %1, %2, %0;" : "+l"(d) : "l"(a), "l"(b));
}

// ---------------- prep: Wc = W2 @ W1 (store transposed), bc = W2 @ b1 ----
__global__ void wct_kernel(const float* __restrict__ W1,   // [HID, OUT]
                           const float* __restrict__ W2) { // [OUT, HID]
    int o = blockIdx.x;     // output row of Wc
    int k = threadIdx.x;    // inner col
    const float* w2row = W2 + (size_t)o * HIDD;
    float acc = 0.f;
    #pragma unroll 8
    for (int h = 0; h < HIDD; ++h)
        acc += w2row[h] * W1[(size_t)h * OUTD + k];
    g_WcT[k * OUTD + o] = acc;
}

__global__ void bc_kernel(const float* __restrict__ W2, const float* __restrict__ b1) {
    int o = threadIdx.x;
    float acc = 0.f;
    #pragma unroll 8
    for (int h = 0; h < HIDD; ++h)
        acc += W2[(size_t)o * HIDD + h] * b1[h];
    g_bc[o] = acc;
}

// ---------------- zero the accumulators (graph replays need this) --------
__global__ void zero_kernel() {
    int i = blockIdx.x * blockDim.x + threadIdx.x;
    int stride = gridDim.x * blockDim.x;
    const int n4 = NNODES * (OUTD / 4);
    for (int j = i; j < n4; j += stride) g_S4[j] = make_float4(0.f, 0.f, 0.f, 0.f);
    for (int j = i; j < NNODES; j += stride) g_cnt[j] = 0.f;
}

// ---------------- scatter: S[index[e]] += msg[e], cnt[index[e]] += 1 -----
// One warp per edge (32 lanes x float4 = 128 floats). red.global.add.v4.f32
// keeps the reduction in L2 (S is 25.6 MB, fits) with no return traffic.
__global__ void scatter_kernel(const float4* __restrict__ msg4,
                               const int* __restrict__ index, int E) {
    int lane  = threadIdx.x & 31;
    int warp  = (blockIdx.x * blockDim.x + threadIdx.x) >> 5;
    int nwarp = (gridDim.x * blockDim.x) >> 5;
    for (int e = warp; e < E; e += nwarp) {
        int n = __ldg(index + e);
        float4 v = __ldg(msg4 + (size_t)e * 32 + lane);
        float* dst = (float*)&g_S4[(size_t)n * 32 + lane];
        asm volatile("red.global.add.v4.f32 [%0], {%1, %2, %3, %4};"
                     :: "l"(dst), "f"(v.x), "f"(v.y), "f"(v.z), "f"(v.w)
                     : "memory");
        if (lane == 0) atomicAdd(&g_cnt[n], 1.0f);
    }
}

// ---------------- final: out = leaky(S @ WcT + cnt*bc + b2) --------------
// Block tile: 64 rows x 128 cols, K split in two 64-chunks (48 KB static smem).
// Thread tile: 4 rows x 8 cols via 16 packed f32x2 accumulators.
__global__ void __launch_bounds__(256) final_kernel(const float* __restrict__ b2,
                                                    float* __restrict__ out, int N) {
    __shared__ float sW[64 * 128];   // WcT chunk [kk][o]
    __shared__ float sS[64 * 64];    // S rows chunk [r][kk]

    const int t    = threadIdx.x;
    const int row0 = blockIdx.x * 64;
    const int tx   = t & 15;         // col group
    const int ty   = t >> 4;         // row group
    const int c0   = tx * 8;
    const int r0   = ty * 4;

    unsigned long long acc[4][4];
    #pragma unroll
    for (int i = 0; i < 4; ++i)
        #pragma unroll
        for (int j = 0; j < 4; ++j) acc[i][j] = 0ull;

    const float4* S4 = (const float4*)g_S4;

    for (int kb = 0; kb < 128; kb += 64) {
        // stage WcT chunk: 8192 floats
        float4* sW4 = (float4*)sW;
        const float4* W4 = (const float4*)g_WcT;
        #pragma unroll
        for (int i = 0; i < 8; ++i) {
            int f = t + 256 * i;            // kk*32 + o/4
            sW4[f] = W4[kb * 32 + f];
        }
        // stage S chunk: 4096 floats
        float4* sS4 = (float4*)sS;
        #pragma unroll
        for (int i = 0; i < 4; ++i) {
            int f = t + 256 * i;            // r*16 + c
            int r = f >> 4, c = f & 15;
            int n = row0 + r;
            float4 v = make_float4(0.f, 0.f, 0.f, 0.f);
            if (n < N) v = __ldg(S4 + (size_t)n * 32 + (kb >> 2) + c);
            sS4[f] = v;
        }
        __syncthreads();

        #pragma unroll 4
        for (int k = 0; k < 64; ++k) {
            float4 wa = *(const float4*)(sW + k * 128 + c0);
            float4 wb = *(const float4*)(sW + k * 128 + c0 + 4);
            unsigned long long w0 = pack2(wa.x, wa.y);
            unsigned long long w1 = pack2(wa.z, wa.w);
            unsigned long long w2 = pack2(wb.x, wb.y);
            unsigned long long w3 = pack2(wb.z, wb.w);
            #pragma unroll
            for (int i = 0; i < 4; ++i) {
                float s = sS[(r0 + i) * 64 + k];
                unsigned long long ss = pack2(s, s);
                ffma2(acc[i][0], ss, w0);
                ffma2(acc[i][1], ss, w1);
                ffma2(acc[i][2], ss, w2);
                ffma2(acc[i][3], ss, w3);
            }
        }
        __syncthreads();
    }

    // epilogue: + cnt*bc + b2, LeakyReLU(0.01), store
    #pragma unroll
    for (int i = 0; i < 4; ++i) {
        int n = row0 + r0 + i;
        if (n >= N) continue;
        float cnt = g_cnt[n];
        float res[8];
        #pragma unroll
        for (int j = 0; j < 4; ++j) {
            float lo, hi;
            unpack2(acc[i][j], lo, hi);
            int c = c0 + 2 * j;
            float v0 = lo + cnt * g_bc[c]     + __ldg(b2 + c);
            float v1 = hi + cnt * g_bc[c + 1] + __ldg(b2 + c + 1);
            res[2 * j]     = (v0 >= 0.f) ? v0 : 0.01f * v0;
            res[2 * j + 1] = (v1 >= 0.f) ? v1 : 0.01f * v1;
        }
        float4* o4 = (float4*)(out + (size_t)n * OUTD + c0);
        o4[0] = make_float4(res[0], res[1], res[2], res[3]);
        o4[1] = make_float4(res[4], res[5], res[6], res[7]);
    }
}

// ---------------- launch -------------------------------------------------
extern "C" void kernel_launch(void* const* d_in, const int* in_sizes, int n_in,
                              void* d_out, int out_size) {
    // metadata order: msg, x_i, x_j, e_ij, index, num_nodes, W1, b1, W2, b2
    const float* msg   = (const float*)d_in[0];
    const int*   index = (const int*)  d_in[4];
    const float* W1    = (const float*)d_in[6];
    const float* b1    = (const float*)d_in[7];
    const float* W2    = (const float*)d_in[8];
    const float* b2    = (const float*)d_in[9];
    float* out = (float*)d_out;

    int E = in_sizes[4];
    int N = out_size / OUTD;
    if (N > NNODES) N = NNODES;

    wct_kernel<<<OUTD, OUTD>>>(W1, W2);
    bc_kernel<<<1, OUTD>>>(W2, b1);
    zero_kernel<<<2048, 256>>>();
    scatter_kernel<<<12500, 256>>>((const float4*)msg, index, E);
    final_kernel<<<(N + 63) / 64, 256>>>(b2, out, N);
}